// round 12
// baseline (speedup 1.0000x reference)
#include <cuda_runtime.h>
#include <cuda_fp16.h>
#include <cstdint>
#include <math.h>

// Problem constants
#define NB 64
#define NSX 128
#define NT 128
#define NE 128
#define NH 256
#define NV 32000
#define G4 1024

// ---------------- device scratch ----------------
__device__ float  g_xg[8192 * G4];          // x-gates fp32 (32 MB)
__device__ __half g_xh[8192 * NE];          // fp16 embedded inputs
__device__ __half g_yh[8192 * NH];          // fp16 layer outputs
__device__ float  g_hF[2 * NB * NH];
__device__ float  g_cF[2 * NB * NH];
__device__ __half g_w0[G4 * NE];            // enc Wih0 fp16
__device__ __half g_w1[G4 * NH];            // enc Wih1
__device__ __half g_w2[G4 * NE];            // dec Wih0
__device__ __half g_w3[G4 * NH];            // dec Wih1
__device__ __half g_fw[NV * NH];            // fc_W fp16

// ---------------- small helpers ----------------
__device__ __forceinline__ uint32_t smem_u32(const void* p) {
    uint32_t a;
    asm("{ .reg .u64 t; cvta.to.shared.u64 t, %1; cvt.u32.u64 %0, t; }"
        : "=r"(a) : "l"(p));
    return a;
}
__device__ __forceinline__ void cp16(uint32_t dst, const void* src) {
    asm volatile("cp.async.cg.shared.global [%0], [%1], 16;" :: "r"(dst), "l"(src));
}
__device__ __forceinline__ void ldsm4(uint32_t& r0, uint32_t& r1, uint32_t& r2,
                                      uint32_t& r3, uint32_t addr) {
    asm volatile("ldmatrix.sync.aligned.m8n8.x4.shared.b16 {%0,%1,%2,%3}, [%4];"
                 : "=r"(r0), "=r"(r1), "=r"(r2), "=r"(r3) : "r"(addr));
}
__device__ __forceinline__ void mma16816(float* c, const uint32_t* a,
                                         uint32_t b0, uint32_t b1) {
    asm volatile(
        "mma.sync.aligned.m16n8k16.row.col.f32.f16.f16.f32 "
        "{%0,%1,%2,%3}, {%4,%5,%6,%7}, {%8,%9}, {%0,%1,%2,%3};"
        : "+f"(c[0]), "+f"(c[1]), "+f"(c[2]), "+f"(c[3])
        : "r"(a[0]), "r"(a[1]), "r"(a[2]), "r"(a[3]), "r"(b0), "r"(b1));
}

// ---------------- fused conversion kernel ----------------
__global__ void f2h_all_kernel(const float* __restrict__ e0, const float* __restrict__ e1,
                               const float* __restrict__ q0, const float* __restrict__ q1,
                               const float* __restrict__ fw,
                               __half* __restrict__ w0, __half* __restrict__ w1,
                               __half* __restrict__ w2, __half* __restrict__ w3,
                               __half* __restrict__ wf) {
    int i = (blockIdx.x * blockDim.x + threadIdx.x) * 4;
    const float* s; __half* d; int off;
    if (i < 131072)      { s = e0; d = w0; off = i; }
    else if (i < 393216) { s = e1; d = w1; off = i - 131072; }
    else if (i < 524288) { s = q0; d = w2; off = i - 393216; }
    else if (i < 786432) { s = q1; d = w3; off = i - 524288; }
    else                 { s = fw; d = wf; off = i - 786432;
                           if (off >= 8192000) return; }
    float4 v = *(const float4*)(s + off);
    __half2* o = (__half2*)(d + off);
    o[0] = __floats2half2_rn(v.x, v.y);
    o[1] = __floats2half2_rn(v.z, v.w);
}

// ---------------- embedding kernels ----------------
__global__ void embed_src_kernel(const int* __restrict__ src,
                                 const float* __restrict__ emb,
                                 __half* __restrict__ out) {
    int idx = blockIdx.x * blockDim.x + threadIdx.x;
    if (idx >= NSX * NB * NE) return;
    int e = idx % NE;
    int r = idx / NE;
    int b = r % NB;
    int s = r / NB;
    out[(size_t)r * NE + e] = __float2half(emb[(size_t)src[b * NSX + s] * NE + e]);
}

__global__ void embed_trg_kernel(const int* __restrict__ trg,
                                 const float* __restrict__ emb,
                                 __half* __restrict__ out) {
    int idx = blockIdx.x * blockDim.x + threadIdx.x;
    if (idx >= 127 * NB * NE) return;
    int e = idx % NE;
    int r = idx / NE;
    int b = r % NB;
    int t = r / NB;
    int tok = (t == 0) ? 1 : trg[b * NT + t];
    out[(size_t)r * NE + e] = __float2half(emb[(size_t)tok * NE + e]);
}

__global__ void zero_first_kernel(float* __restrict__ out) {
    int idx = blockIdx.x * blockDim.x + threadIdx.x;
    if (idx >= NB * NV) return;
    int v = idx % NV;
    int b = idx / NV;
    out[(size_t)b * NT * NV + v] = 0.f;
}

// ---------------- fp16 tensor-core GEMM for gates (3 CTAs/SM, low-reg) ----------------
#define GSTAGE 24576                  // A 16KB + B 8KB
#define GSMEM  (3 * GSTAGE)

__global__ void __launch_bounds__(256, 3)
gemm16_kernel(const __half* __restrict__ A, const __half* __restrict__ W,
              const float* __restrict__ b0, const float* __restrict__ b1,
              float* __restrict__ C, int N, int K) {
    extern __shared__ char smbuf[];
    const uint32_t sb = smem_u32(smbuf);
    const int tid = threadIdx.x;
    const int lane = tid & 31;
    const int wid = tid >> 5;
    const int warp_m = wid & 3;
    const int warp_n = wid >> 2;
    const int m0 = blockIdx.y * 128;
    const int n0 = blockIdx.x * 64;
    const int KT = K >> 6;

    float acc[2][4][4];
#pragma unroll
    for (int i = 0; i < 2; i++)
#pragma unroll
        for (int j = 0; j < 4; j++)
#pragma unroll
            for (int q = 0; q < 4; q++) acc[i][j][q] = 0.f;

    auto loadStage = [&](int kt, int s) {
        const uint32_t st = sb + (uint32_t)s * GSTAGE;
        const __half* Ag = A + (size_t)m0 * K + kt * 64;
        const __half* Wg = W + (size_t)n0 * K + kt * 64;
#pragma unroll
        for (int i = 0; i < 4; i++) {
            int idx = i * 256 + tid;
            int row = idx >> 3, c = idx & 7;
            uint32_t off = (uint32_t)(row * 128 + ((c ^ (row & 7)) << 4));
            cp16(st + off, Ag + (size_t)row * K + c * 8);
        }
#pragma unroll
        for (int i = 0; i < 2; i++) {
            int idx = i * 256 + tid;
            int row = idx >> 3, c = idx & 7;
            uint32_t off = (uint32_t)(row * 128 + ((c ^ (row & 7)) << 4));
            cp16(st + 16384 + off, Wg + (size_t)row * K + c * 8);
        }
        asm volatile("cp.async.commit_group;" ::: "memory");
    };

    loadStage(0, 0);
    loadStage(1, 1);
    asm volatile("cp.async.wait_group 1;" ::: "memory");
    __syncthreads();

    for (int kt = 0; kt < KT; kt++) {
        const int s = kt % 3;
        if (kt + 2 < KT) loadStage(kt + 2, (kt + 2) % 3);
        const uint32_t stA = sb + (uint32_t)s * GSTAGE;
        const uint32_t stB = stA + 16384;
#pragma unroll
        for (int k16 = 0; k16 < 4; k16++) {
            uint32_t a[2][4];
#pragma unroll
            for (int mt = 0; mt < 2; mt++) {
                int row = warp_m * 32 + mt * 16 + (lane & 15);
                int ch = k16 * 2 + (lane >> 4);
                ldsm4(a[mt][0], a[mt][1], a[mt][2], a[mt][3],
                      stA + row * 128 + ((ch ^ (row & 7)) << 4));
            }
#pragma unroll
            for (int p = 0; p < 2; p++) {
                int nrow = warp_n * 32 + p * 16 + ((lane >> 4) & 1) * 8 + (lane & 7);
                int ch = k16 * 2 + ((lane >> 3) & 1);
                uint32_t br0, br1, br2, br3;
                ldsm4(br0, br1, br2, br3,
                      stB + nrow * 128 + ((ch ^ (nrow & 7)) << 4));
#pragma unroll
                for (int mt = 0; mt < 2; mt++) {
                    mma16816(acc[mt][2 * p],     a[mt], br0, br1);
                    mma16816(acc[mt][2 * p + 1], a[mt], br2, br3);
                }
            }
        }
        asm volatile("cp.async.wait_group 1;" ::: "memory");
        __syncthreads();
    }

    const int lrow = lane >> 2;
    const int lcol = (lane & 3) * 2;
#pragma unroll
    for (int nt = 0; nt < 4; nt++) {
        const int n = n0 + warp_n * 32 + nt * 8 + lcol;
        float bv0 = b0[n] + b1[n];
        float bv1 = b0[n + 1] + b1[n + 1];
#pragma unroll
        for (int mt = 0; mt < 2; mt++) {
            const int mbase = m0 + warp_m * 32 + mt * 16 + lrow;
#pragma unroll
            for (int half = 0; half < 2; half++) {
                const int m = mbase + half * 8;
                float2 v;
                v.x = acc[mt][nt][half * 2 + 0] + bv0;
                v.y = acc[mt][nt][half * 2 + 1] + bv1;
                *(float2*)(C + (size_t)m * N + n) = v;
            }
        }
    }
}

// ---------------- FC GEMM: A-resident, N-streaming ----------------
// Block: 128 M-rows, FULL K=256 of A in smem (4 pages x 16KB, swizzled).
// Streams 10 N-tiles of 64 (W 32KB each, 2 buffers, prefetch dist 1).
// grid (50 N-strips, 64 M-tiles). Row remap: m=t*64+b -> out[(b*128+t+1)*NV+n].
#define FCSM_A 0
#define FCSM_W 65536                   // 2 x 32768
#define FC_SMEM (65536 + 2 * 32768)
#define FC_NTILES 10

__global__ void __launch_bounds__(256, 1)
fc_gemm_kernel(const __half* __restrict__ A, const __half* __restrict__ W,
               const float* __restrict__ bias, float* __restrict__ C) {
    extern __shared__ char smbuf[];
    const uint32_t sb = smem_u32(smbuf);
    const int tid = threadIdx.x;
    const int lane = tid & 31;
    const int wid = tid >> 5;
    const int warp_m = wid & 3;        // 4 warps over M (32 rows)
    const int warp_n = wid >> 2;       // 2 warps over N (32 cols)
    const int m0 = blockIdx.y * 128;
    const int nbase = blockIdx.x * (FC_NTILES * 64);

    // ---- load A (128 x 256 fp16 = 64KB, 4 pages of 128rows x 128B) ----
#pragma unroll
    for (int i = 0; i < 16; i++) {
        int idx = i * 256 + tid;           // 4096 16B chunks
        int page = idx >> 10;
        int ip = idx & 1023;
        int row = ip >> 3, c = ip & 7;
        uint32_t off = (uint32_t)(page * 16384 + row * 128 + ((c ^ (row & 7)) << 4));
        cp16(sb + FCSM_A + off, A + (size_t)(m0 + row) * 256 + page * 64 + c * 8);
    }

    auto loadW = [&](int nt, int buf) {
        const __half* Wg = W + (size_t)(nbase + nt * 64) * 256;
        const uint32_t wb = sb + FCSM_W + (uint32_t)buf * 32768;
#pragma unroll
        for (int i = 0; i < 8; i++) {
            int idx = i * 256 + tid;       // 2048 16B chunks
            int page = idx >> 9;
            int ip = idx & 511;
            int row = ip >> 3, c = ip & 7;
            uint32_t off = (uint32_t)(page * 8192 + row * 128 + ((c ^ (row & 7)) << 4));
            cp16(wb + off, Wg + (size_t)row * 256 + page * 64 + c * 8);
        }
        asm volatile("cp.async.commit_group;" ::: "memory");
    };

    loadW(0, 0);                           // group 0 (A + W0)
    loadW(1, 1);                           // group 1 (W1)

    const int lrow = lane >> 2;
    const int lcol = (lane & 3) * 2;

    for (int nt = 0; nt < FC_NTILES; nt++) {
        if (nt < FC_NTILES - 1)
            asm volatile("cp.async.wait_group 1;" ::: "memory");
        else
            asm volatile("cp.async.wait_group 0;" ::: "memory");
        __syncthreads();

        float acc[2][4][4];
#pragma unroll
        for (int i = 0; i < 2; i++)
#pragma unroll
            for (int j = 0; j < 4; j++)
#pragma unroll
                for (int q = 0; q < 4; q++) acc[i][j][q] = 0.f;

        const uint32_t wb = sb + FCSM_W + (uint32_t)(nt & 1) * 32768;
#pragma unroll
        for (int kt = 0; kt < 4; kt++) {
            const uint32_t stA = sb + FCSM_A + (uint32_t)kt * 16384;
            const uint32_t stW = wb + (uint32_t)kt * 8192;
#pragma unroll
            for (int k16 = 0; k16 < 4; k16++) {
                uint32_t a[2][4];
#pragma unroll
                for (int mt = 0; mt < 2; mt++) {
                    int row = warp_m * 32 + mt * 16 + (lane & 15);
                    int ch = k16 * 2 + (lane >> 4);
                    ldsm4(a[mt][0], a[mt][1], a[mt][2], a[mt][3],
                          stA + row * 128 + ((ch ^ (row & 7)) << 4));
                }
#pragma unroll
                for (int p = 0; p < 2; p++) {
                    int nrow = warp_n * 32 + p * 16 + ((lane >> 4) & 1) * 8 + (lane & 7);
                    int ch = k16 * 2 + ((lane >> 3) & 1);
                    uint32_t br0, br1, br2, br3;
                    ldsm4(br0, br1, br2, br3,
                          stW + nrow * 128 + ((ch ^ (nrow & 7)) << 4));
#pragma unroll
                    for (int mt = 0; mt < 2; mt++) {
                        mma16816(acc[mt][2 * p],     a[mt], br0, br1);
                        mma16816(acc[mt][2 * p + 1], a[mt], br2, br3);
                    }
                }
            }
        }
        __syncthreads();                   // all warps done reading buf (nt&1)
        if (nt + 2 < FC_NTILES) loadW(nt + 2, nt & 1);

        // ---- epilogue for this N-tile (registers only; overlaps next loads) ----
        const int n0 = nbase + nt * 64;
#pragma unroll
        for (int q = 0; q < 4; q++) {
            const int n = n0 + warp_n * 32 + q * 8 + lcol;
            float bv0 = bias[n];
            float bv1 = bias[n + 1];
#pragma unroll
            for (int mt = 0; mt < 2; mt++) {
                const int mbase = m0 + warp_m * 32 + mt * 16 + lrow;
#pragma unroll
                for (int half = 0; half < 2; half++) {
                    const int m = mbase + half * 8;
                    if (m < 8128) {
                        int t = m >> 6, b = m & 63;
                        float2 v;
                        v.x = acc[mt][q][half * 2 + 0] + bv0;
                        v.y = acc[mt][q][half * 2 + 1] + bv1;
                        *(float2*)(C + ((size_t)(b * 128 + t + 1)) * NV + n) = v;
                    }
                }
            }
        }
    }
}

// ---------------- clustered HMMA LSTM recurrence ----------------
#define RECSM_W   0
#define RECSM_H0  65536
#define RECSM_H1  (65536 + 8192)
#define RECSM_SG  (65536 + 16384)
#define REC_SMEM_BYTES (65536 + 16384 + 2048)

__global__ void __cluster_dims__(8, 1, 1) __launch_bounds__(256, 1)
lstm_rec_kernel(const float* __restrict__ xg,
                const float* __restrict__ Whh,
                const float* __restrict__ hInit,
                const float* __restrict__ cInit,
                __half* __restrict__ ysh,
                float* __restrict__ hFin,
                float* __restrict__ cFin,
                int nSteps) {
    extern __shared__ char smb[];
    const uint32_t sb = smem_u32(smb);
    float* sg = (float*)(smb + RECSM_SG);

    const int tid = threadIdx.x;
    const int lane = tid & 31;
    const int wid = tid >> 5;
    uint32_t rank;
    asm("mov.u32 %0, %%cluster_ctarank;" : "=r"(rank));
    const int bt = blockIdx.x >> 3;
    const int n0 = (int)rank * 32;

    for (int i = tid; i < 4096; i += 256)
        ((uint32_t*)(smb + RECSM_H0))[i] = 0u;

#pragma unroll 4
    for (int it = 0; it < 32; it++) {
        int idx = it * 256 + tid;
        int r = idx >> 6, c4 = idx & 63;
        int grow = (r >> 5) * 256 + n0 + (r & 31);
        float4 v = *(const float4*)(Whh + (size_t)grow * 256 + c4 * 4);
        int k = c4 * 4;
        int chunk = (k >> 3) ^ (r & 7);
        __half2* d = (__half2*)(smb + RECSM_W + r * 512 + chunk * 16 + (k & 7) * 2);
        d[0] = __floats2half2_rn(v.x, v.y);
        d[1] = __floats2half2_rn(v.z, v.w);
    }
    __syncthreads();

    if (hInit) {
        int b = tid >> 6, k = (tid & 63) * 4;
        float4 v = *(const float4*)(hInit + (size_t)(bt * 4 + b) * 256 + k);
        int chunk = (k >> 3) ^ b;
        __half2* d = (__half2*)(smb + RECSM_H0 + b * 512 + chunk * 16 + (k & 7) * 2);
        d[0] = __floats2half2_rn(v.x, v.y);
        d[1] = __floats2half2_rn(v.z, v.w);
    }

    const int fb = tid >> 5;
    const int fn = tid & 31;
    const int bG = bt * 4 + fb;
    float cS = 0.f;
    if (tid < 128 && cInit) cS = cInit[bG * 256 + n0 + fn];

    uint32_t remA[8], remB[8];
    if (tid < 128) {
        int kg = n0 + fn;
        uint32_t off = (uint32_t)(fb * 512 + (((kg >> 3) ^ fb) << 4) + (kg & 7) * 2);
        uint32_t la = sb + RECSM_H0 + off;
        uint32_t lb = sb + RECSM_H1 + off;
#pragma unroll
        for (int r = 0; r < 8; r++) {
            asm("mapa.shared::cluster.u32 %0, %1, %2;" : "=r"(remA[r]) : "r"(la), "r"(r));
            asm("mapa.shared::cluster.u32 %0, %1, %2;" : "=r"(remB[r]) : "r"(lb), "r"(r));
        }
    }
    __syncthreads();
    asm volatile("barrier.cluster.arrive.aligned;" ::: "memory");
    asm volatile("barrier.cluster.wait.aligned;" ::: "memory");

    const int nrow = wid * 16 + ((lane >> 4) & 1) * 8 + (lane & 7);
    const uint32_t bAddrBase = sb + RECSM_W + nrow * 512;
    const int brow7 = nrow & 7;
    const int arow = lane & 15;
    const int asel = lane >> 4;

    int p = 0;
    for (int step = 0; step < nSteps; step++) {
        float gi = 0.f, gf = 0.f, gg = 0.f, go = 0.f;
        size_t row = 0;
        if (tid < 128) {
            row = (size_t)step * 64 + bG;
            const float* xr = xg + row * 1024 + n0 + fn;
            gi = xr[0]; gf = xr[256]; gg = xr[512]; go = xr[768];
        }

        const uint32_t hbase = sb + (p ? RECSM_H1 : RECSM_H0) + arow * 512;
        const int arow7 = arow & 7;

        float acc0[4] = {0.f, 0.f, 0.f, 0.f};
        float acc1[4] = {0.f, 0.f, 0.f, 0.f};
#pragma unroll
        for (int kk = 0; kk < 16; kk++) {
            uint32_t a[4];
            ldsm4(a[0], a[1], a[2], a[3],
                  hbase + (uint32_t)(((kk * 2 + asel) ^ arow7) << 4));
            uint32_t b0, b1, b2, b3;
            ldsm4(b0, b1, b2, b3,
                  bAddrBase + (uint32_t)(((kk * 2 + ((lane >> 3) & 1)) ^ brow7) << 4));
            mma16816(acc0, a, b0, b1);
            mma16816(acc1, a, b2, b3);
        }

        if (lane < 16) {
            int g = wid >> 1, b = lane >> 2;
            int jb = (wid & 1) * 16 + (lane & 3) * 2;
            *(float2*)&sg[(g * 4 + b) * 32 + jb] = make_float2(acc0[0], acc0[1]);
            *(float2*)&sg[(g * 4 + b) * 32 + jb + 8] = make_float2(acc1[0], acc1[1]);
        }
        __syncthreads();

        float h = 0.f;
        if (tid < 128) {
            gi += sg[(0 * 4 + fb) * 32 + fn];
            gf += sg[(1 * 4 + fb) * 32 + fn];
            gg += sg[(2 * 4 + fb) * 32 + fn];
            go += sg[(3 * 4 + fb) * 32 + fn];
            float iv = 1.f / (1.f + expf(-gi));
            float fv = 1.f / (1.f + expf(-gf));
            float gv = tanhf(gg);
            float ov = 1.f / (1.f + expf(-go));
            cS = fv * cS + iv * gv;
            h = ov * tanhf(cS);

            unsigned short hu = __half_as_ushort(__float2half(h));
#pragma unroll
            for (int r = 0; r < 8; r++) {
                uint32_t ra = p ? remA[r] : remB[r];
                asm volatile("st.shared::cluster.u16 [%0], %1;" :: "r"(ra), "h"(hu) : "memory");
            }
        }

        asm volatile("barrier.cluster.arrive.aligned;" ::: "memory");
        if (tid < 128) {
            if (ysh) ysh[row * 256 + n0 + fn] = __float2half(h);
            if (step == nSteps - 1) {
                if (hFin) hFin[bG * 256 + n0 + fn] = h;
                if (cFin) cFin[bG * 256 + n0 + fn] = cS;
            }
        }
        asm volatile("barrier.cluster.wait.aligned;" ::: "memory");
        p ^= 1;
    }
}

// ---------------- host launch ----------------
extern "C" void kernel_launch(void* const* d_in, const int* in_sizes, int n_in,
                              void* d_out, int out_size) {
    const int*   src     = (const int*)d_in[0];
    const int*   trg     = (const int*)d_in[1];
    const float* enc_emb = (const float*)d_in[2];
    const float* dec_emb = (const float*)d_in[3];
    const float* eWih0 = (const float*)d_in[4],  *eWhh0 = (const float*)d_in[5];
    const float* ebih0 = (const float*)d_in[6],  *ebhh0 = (const float*)d_in[7];
    const float* eWih1 = (const float*)d_in[8],  *eWhh1 = (const float*)d_in[9];
    const float* ebih1 = (const float*)d_in[10], *ebhh1 = (const float*)d_in[11];
    const float* dWih0 = (const float*)d_in[12], *dWhh0 = (const float*)d_in[13];
    const float* dbih0 = (const float*)d_in[14], *dbhh0 = (const float*)d_in[15];
    const float* dWih1 = (const float*)d_in[16], *dWhh1 = (const float*)d_in[17];
    const float* dbih1 = (const float*)d_in[18], *dbhh1 = (const float*)d_in[19];
    const float* fcW   = (const float*)d_in[20], *fcb   = (const float*)d_in[21];
    float* out = (float*)d_out;

    float *pxg, *phF, *pcF;
    __half *pxh, *pyh, *pw0, *pw1, *pw2, *pw3, *pfw;
    cudaGetSymbolAddress((void**)&pxg,   g_xg);
    cudaGetSymbolAddress((void**)&phF,   g_hF);
    cudaGetSymbolAddress((void**)&pcF,   g_cF);
    cudaGetSymbolAddress((void**)&pxh,   g_xh);
    cudaGetSymbolAddress((void**)&pyh,   g_yh);
    cudaGetSymbolAddress((void**)&pw0,   g_w0);
    cudaGetSymbolAddress((void**)&pw1,   g_w1);
    cudaGetSymbolAddress((void**)&pw2,   g_w2);
    cudaGetSymbolAddress((void**)&pw3,   g_w3);
    cudaGetSymbolAddress((void**)&pfw,   g_fw);

    cudaFuncSetAttribute(lstm_rec_kernel,
                         cudaFuncAttributeMaxDynamicSharedMemorySize, REC_SMEM_BYTES);
    cudaFuncSetAttribute(gemm16_kernel,
                         cudaFuncAttributeMaxDynamicSharedMemorySize, GSMEM);
    cudaFuncSetAttribute(fc_gemm_kernel,
                         cudaFuncAttributeMaxDynamicSharedMemorySize, FC_SMEM);

    // fused weight conversion + output-row-0 zeroing
    f2h_all_kernel<<<(8978432 / 4 + 255) / 256, 256>>>(eWih0, eWih1, dWih0, dWih1, fcW,
                                                       pw0, pw1, pw2, pw3, pfw);
    zero_first_kernel<<<(NB * NV + 255) / 256, 256>>>(out);

    // ---- Encoder ----
    embed_src_kernel<<<(NSX * NB * NE + 255) / 256, 256>>>(src, enc_emb, pxh);
    gemm16_kernel<<<dim3(16, 64), 256, GSMEM>>>(pxh, pw0, ebih0, ebhh0, pxg,
                                                G4, NE);
    lstm_rec_kernel<<<128, 256, REC_SMEM_BYTES>>>(pxg, eWhh0, nullptr, nullptr,
                                                  pyh, phF, pcF, 128);
    gemm16_kernel<<<dim3(16, 64), 256, GSMEM>>>(pyh, pw1, ebih1, ebhh1, pxg,
                                                G4, NH);
    lstm_rec_kernel<<<128, 256, REC_SMEM_BYTES>>>(pxg, eWhh1, nullptr, nullptr,
                                                  nullptr, phF + NB * NH, pcF + NB * NH,
                                                  128);

    // ---- Decoder (teacher forced) ----
    embed_trg_kernel<<<(127 * NB * NE + 255) / 256, 256>>>(trg, dec_emb, pxh);
    gemm16_kernel<<<dim3(16, 64), 256, GSMEM>>>(pxh, pw2, dbih0, dbhh0, pxg,
                                                G4, NE);
    lstm_rec_kernel<<<128, 256, REC_SMEM_BYTES>>>(pxg, dWhh0, phF, pcF,
                                                  pyh, nullptr, nullptr, 127);
    gemm16_kernel<<<dim3(16, 64), 256, GSMEM>>>(pyh, pw3, dbih1, dbhh1, pxg,
                                                G4, NH);
    lstm_rec_kernel<<<128, 256, REC_SMEM_BYTES>>>(pxg, dWhh1, phF + NB * NH, pcF + NB * NH,
                                                  pyh, nullptr, nullptr, 127);

    // ---- Output: A-resident N-streaming FC ----
    fc_gemm_kernel<<<dim3(50, 64), 256, FC_SMEM>>>(pyh, pfw, fcb, out);
}

// round 14
// speedup vs baseline: 1.0548x; 1.0548x over previous
#include <cuda_runtime.h>
#include <cuda_fp16.h>
#include <cstdint>
#include <math.h>

// Problem constants
#define NB 64
#define NSX 128
#define NT 128
#define NE 128
#define NH 256
#define NV 32000
#define G4 1024
#define CH1 64                  // decoder chunk-1 steps
#define CH2 63                  // decoder chunk-2 steps
#define OFFR 4096               // rows in chunk 1 (CH1*64)

// ---------------- device scratch ----------------
__device__ float  g_xg [8192 * G4];         // xg buffer A (32 MB)
__device__ float  g_xg2[8192 * G4];         // xg buffer B (32 MB)
__device__ __half g_xh [8192 * NE];         // fp16 embedded enc inputs
__device__ __half g_xh2[8192 * NE];         // fp16 embedded dec inputs
__device__ __half g_yh[8192 * NH];          // fp16 layer outputs
__device__ float  g_hF[2 * NB * NH];
__device__ float  g_cF[2 * NB * NH];
__device__ float  g_hT[4 * NB * NH];        // chunk-carry states: hT0,cT0,hT1,cT1
__device__ __half g_w0[G4 * NE];
__device__ __half g_w1[G4 * NH];
__device__ __half g_w2[G4 * NE];
__device__ __half g_w3[G4 * NH];
__device__ __half g_fw[NV * NH];

// ---------------- stream/event resources (created pre-main, no capture impact) ----
struct StreamHolder {
    cudaStream_t s = nullptr;
    cudaEvent_t e0 = nullptr, e1 = nullptr, e2 = nullptr;
    StreamHolder() {
        cudaStreamCreateWithFlags(&s, cudaStreamNonBlocking);
        cudaEventCreateWithFlags(&e0, cudaEventDisableTiming);
        cudaEventCreateWithFlags(&e1, cudaEventDisableTiming);
        cudaEventCreateWithFlags(&e2, cudaEventDisableTiming);
    }
};
static StreamHolder g_sh;

// ---------------- small helpers ----------------
__device__ __forceinline__ uint32_t smem_u32(const void* p) {
    uint32_t a;
    asm("{ .reg .u64 t; cvta.to.shared.u64 t, %1; cvt.u32.u64 %0, t; }"
        : "=r"(a) : "l"(p));
    return a;
}
__device__ __forceinline__ void cp16(uint32_t dst, const void* src) {
    asm volatile("cp.async.cg.shared.global [%0], [%1], 16;" :: "r"(dst), "l"(src));
}
__device__ __forceinline__ void ldsm4(uint32_t& r0, uint32_t& r1, uint32_t& r2,
                                      uint32_t& r3, uint32_t addr) {
    asm volatile("ldmatrix.sync.aligned.m8n8.x4.shared.b16 {%0,%1,%2,%3}, [%4];"
                 : "=r"(r0), "=r"(r1), "=r"(r2), "=r"(r3) : "r"(addr));
}
__device__ __forceinline__ void mma16816(float* c, const uint32_t* a,
                                         uint32_t b0, uint32_t b1) {
    asm volatile(
        "mma.sync.aligned.m16n8k16.row.col.f32.f16.f16.f32 "
        "{%0,%1,%2,%3}, {%4,%5,%6,%7}, {%8,%9}, {%0,%1,%2,%3};"
        : "+f"(c[0]), "+f"(c[1]), "+f"(c[2]), "+f"(c[3])
        : "r"(a[0]), "r"(a[1]), "r"(a[2]), "r"(a[3]), "r"(b0), "r"(b1));
}

// ---------------- fused conversion kernel ----------------
__global__ void f2h_all_kernel(const float* __restrict__ e0, const float* __restrict__ e1,
                               const float* __restrict__ q0, const float* __restrict__ q1,
                               const float* __restrict__ fw,
                               __half* __restrict__ w0, __half* __restrict__ w1,
                               __half* __restrict__ w2, __half* __restrict__ w3,
                               __half* __restrict__ wf) {
    int i = (blockIdx.x * blockDim.x + threadIdx.x) * 4;
    const float* s; __half* d; int off;
    if (i < 131072)      { s = e0; d = w0; off = i; }
    else if (i < 393216) { s = e1; d = w1; off = i - 131072; }
    else if (i < 524288) { s = q0; d = w2; off = i - 393216; }
    else if (i < 786432) { s = q1; d = w3; off = i - 524288; }
    else                 { s = fw; d = wf; off = i - 786432;
                           if (off >= 8192000) return; }
    float4 v = *(const float4*)(s + off);
    __half2* o = (__half2*)(d + off);
    o[0] = __floats2half2_rn(v.x, v.y);
    o[1] = __floats2half2_rn(v.z, v.w);
}

// ---------------- embedding kernels ----------------
__global__ void embed_src_kernel(const int* __restrict__ src,
                                 const float* __restrict__ emb,
                                 __half* __restrict__ out) {
    int idx = blockIdx.x * blockDim.x + threadIdx.x;
    if (idx >= NSX * NB * NE) return;
    int e = idx % NE;
    int r = idx / NE;
    int b = r % NB;
    int s = r / NB;
    out[(size_t)r * NE + e] = __float2half(emb[(size_t)src[b * NSX + s] * NE + e]);
}

__global__ void embed_trg_kernel(const int* __restrict__ trg,
                                 const float* __restrict__ emb,
                                 __half* __restrict__ out) {
    int idx = blockIdx.x * blockDim.x + threadIdx.x;
    if (idx >= 127 * NB * NE) return;
    int e = idx % NE;
    int r = idx / NE;
    int b = r % NB;
    int t = r / NB;
    int tok = (t == 0) ? 1 : trg[b * NT + t];
    out[(size_t)r * NE + e] = __float2half(emb[(size_t)tok * NE + e]);
}

__global__ void zero_first_kernel(float* __restrict__ out) {
    int idx = blockIdx.x * blockDim.x + threadIdx.x;
    if (idx >= NB * NV) return;
    int v = idx % NV;
    int b = idx / NV;
    out[(size_t)b * NT * NV + v] = 0.f;
}

// ---------------- fp16 tensor-core GEMM for gates (fp32 acc) ----------------
#define GSTAGE 24576                  // A 16KB + B 8KB
#define GSMEM  (3 * GSTAGE)

__global__ void __launch_bounds__(256, 3)
gemm16_kernel(const __half* __restrict__ A, const __half* __restrict__ W,
              const float* __restrict__ b0, const float* __restrict__ b1,
              float* __restrict__ C, int N, int K) {
    extern __shared__ char smbuf[];
    const uint32_t sb = smem_u32(smbuf);
    const int tid = threadIdx.x;
    const int lane = tid & 31;
    const int wid = tid >> 5;
    const int warp_m = wid & 3;
    const int warp_n = wid >> 2;
    const int m0 = blockIdx.y * 128;
    const int n0 = blockIdx.x * 64;
    const int KT = K >> 6;

    float acc[2][4][4];
#pragma unroll
    for (int i = 0; i < 2; i++)
#pragma unroll
        for (int j = 0; j < 4; j++)
#pragma unroll
            for (int q = 0; q < 4; q++) acc[i][j][q] = 0.f;

    auto loadStage = [&](int kt, int s) {
        const uint32_t st = sb + (uint32_t)s * GSTAGE;
        const __half* Ag = A + (size_t)m0 * K + kt * 64;
        const __half* Wg = W + (size_t)n0 * K + kt * 64;
#pragma unroll
        for (int i = 0; i < 4; i++) {
            int idx = i * 256 + tid;
            int row = idx >> 3, c = idx & 7;
            uint32_t off = (uint32_t)(row * 128 + ((c ^ (row & 7)) << 4));
            cp16(st + off, Ag + (size_t)row * K + c * 8);
        }
#pragma unroll
        for (int i = 0; i < 2; i++) {
            int idx = i * 256 + tid;
            int row = idx >> 3, c = idx & 7;
            uint32_t off = (uint32_t)(row * 128 + ((c ^ (row & 7)) << 4));
            cp16(st + 16384 + off, Wg + (size_t)row * K + c * 8);
        }
        asm volatile("cp.async.commit_group;" ::: "memory");
    };

    loadStage(0, 0);
    loadStage(1, 1);
    asm volatile("cp.async.wait_group 1;" ::: "memory");
    __syncthreads();

    for (int kt = 0; kt < KT; kt++) {
        const int s = kt % 3;
        if (kt + 2 < KT) loadStage(kt + 2, (kt + 2) % 3);
        const uint32_t stA = sb + (uint32_t)s * GSTAGE;
        const uint32_t stB = stA + 16384;
#pragma unroll
        for (int k16 = 0; k16 < 4; k16++) {
            uint32_t a[2][4];
#pragma unroll
            for (int mt = 0; mt < 2; mt++) {
                int row = warp_m * 32 + mt * 16 + (lane & 15);
                int ch = k16 * 2 + (lane >> 4);
                ldsm4(a[mt][0], a[mt][1], a[mt][2], a[mt][3],
                      stA + row * 128 + ((ch ^ (row & 7)) << 4));
            }
#pragma unroll
            for (int p = 0; p < 2; p++) {
                int nrow = warp_n * 32 + p * 16 + ((lane >> 4) & 1) * 8 + (lane & 7);
                int ch = k16 * 2 + ((lane >> 3) & 1);
                uint32_t br0, br1, br2, br3;
                ldsm4(br0, br1, br2, br3,
                      stB + nrow * 128 + ((ch ^ (nrow & 7)) << 4));
#pragma unroll
                for (int mt = 0; mt < 2; mt++) {
                    mma16816(acc[mt][2 * p],     a[mt], br0, br1);
                    mma16816(acc[mt][2 * p + 1], a[mt], br2, br3);
                }
            }
        }
        asm volatile("cp.async.wait_group 1;" ::: "memory");
        __syncthreads();
    }

    const int lrow = lane >> 2;
    const int lcol = (lane & 3) * 2;
#pragma unroll
    for (int nt = 0; nt < 4; nt++) {
        const int n = n0 + warp_n * 32 + nt * 8 + lcol;
        float bv0 = b0[n] + b1[n];
        float bv1 = b0[n + 1] + b1[n + 1];
#pragma unroll
        for (int mt = 0; mt < 2; mt++) {
            const int mbase = m0 + warp_m * 32 + mt * 16 + lrow;
#pragma unroll
            for (int half = 0; half < 2; half++) {
                const int m = mbase + half * 8;
                float2 v;
                v.x = acc[mt][nt][half * 2 + 0] + bv0;
                v.y = acc[mt][nt][half * 2 + 1] + bv1;
                *(float2*)(C + (size_t)m * N + n) = v;
            }
        }
    }
}

// ---------------- FC GEMM (fp32 acc, K=256, M-tile offset for split halves) ----------------
// logical row m = t*64+b -> out[(b*128 + t + 1)*NV + n], skip m >= 8128
__global__ void __launch_bounds__(256, 3)
fc32_kernel(const __half* __restrict__ A, const __half* __restrict__ W,
            const float* __restrict__ bias, float* __restrict__ C, int mTile0) {
    extern __shared__ char smbuf[];
    const uint32_t sb = smem_u32(smbuf);
    const int tid = threadIdx.x;
    const int lane = tid & 31;
    const int wid = tid >> 5;
    const int warp_m = wid & 3;
    const int warp_n = wid >> 2;
    const int m0 = (mTile0 + blockIdx.y) * 128;
    const int n0 = blockIdx.x * 64;
    const int K = 256;

    float acc[2][4][4];
#pragma unroll
    for (int i = 0; i < 2; i++)
#pragma unroll
        for (int j = 0; j < 4; j++)
#pragma unroll
            for (int q = 0; q < 4; q++) acc[i][j][q] = 0.f;

    auto loadStage = [&](int kt, int s) {
        const uint32_t st = sb + (uint32_t)s * GSTAGE;
        const __half* Ag = A + (size_t)m0 * K + kt * 64;
        const __half* Wg = W + (size_t)n0 * K + kt * 64;
#pragma unroll
        for (int i = 0; i < 4; i++) {
            int idx = i * 256 + tid;
            int row = idx >> 3, c = idx & 7;
            uint32_t off = (uint32_t)(row * 128 + ((c ^ (row & 7)) << 4));
            cp16(st + off, Ag + (size_t)row * K + c * 8);
        }
#pragma unroll
        for (int i = 0; i < 2; i++) {
            int idx = i * 256 + tid;
            int row = idx >> 3, c = idx & 7;
            uint32_t off = (uint32_t)(row * 128 + ((c ^ (row & 7)) << 4));
            cp16(st + 16384 + off, Wg + (size_t)row * K + c * 8);
        }
        asm volatile("cp.async.commit_group;" ::: "memory");
    };

    loadStage(0, 0);
    loadStage(1, 1);
    asm volatile("cp.async.wait_group 1;" ::: "memory");
    __syncthreads();

#pragma unroll
    for (int kt = 0; kt < 4; kt++) {
        const int s = kt % 3;
        if (kt + 2 < 4) loadStage(kt + 2, (kt + 2) % 3);
        const uint32_t stA = sb + (uint32_t)s * GSTAGE;
        const uint32_t stB = stA + 16384;
#pragma unroll
        for (int k16 = 0; k16 < 4; k16++) {
            uint32_t a[2][4];
#pragma unroll
            for (int mt = 0; mt < 2; mt++) {
                int row = warp_m * 32 + mt * 16 + (lane & 15);
                int ch = k16 * 2 + (lane >> 4);
                ldsm4(a[mt][0], a[mt][1], a[mt][2], a[mt][3],
                      stA + row * 128 + ((ch ^ (row & 7)) << 4));
            }
#pragma unroll
            for (int p = 0; p < 2; p++) {
                int nrow = warp_n * 32 + p * 16 + ((lane >> 4) & 1) * 8 + (lane & 7);
                int ch = k16 * 2 + ((lane >> 3) & 1);
                uint32_t br0, br1, br2, br3;
                ldsm4(br0, br1, br2, br3,
                      stB + nrow * 128 + ((ch ^ (nrow & 7)) << 4));
#pragma unroll
                for (int mt = 0; mt < 2; mt++) {
                    mma16816(acc[mt][2 * p],     a[mt], br0, br1);
                    mma16816(acc[mt][2 * p + 1], a[mt], br2, br3);
                }
            }
        }
        asm volatile("cp.async.wait_group 1;" ::: "memory");
        __syncthreads();
    }

    const int lrow = lane >> 2;
    const int lcol = (lane & 3) * 2;
#pragma unroll
    for (int nt = 0; nt < 4; nt++) {
        const int n = n0 + warp_n * 32 + nt * 8 + lcol;
        float bv0 = bias[n];
        float bv1 = bias[n + 1];
#pragma unroll
        for (int mt = 0; mt < 2; mt++) {
            const int mbase = m0 + warp_m * 32 + mt * 16 + lrow;
#pragma unroll
            for (int half = 0; half < 2; half++) {
                const int m = mbase + half * 8;
                if (m < 8128) {
                    int t = m >> 6, b = m & 63;
                    float2 v;
                    v.x = acc[mt][nt][half * 2 + 0] + bv0;
                    v.y = acc[mt][nt][half * 2 + 1] + bv1;
                    *(float2*)(C + ((size_t)(b * 128 + t + 1)) * NV + n) = v;
                }
            }
        }
    }
}

// ---------------- clustered HMMA LSTM recurrence ----------------
#define RECSM_W   0
#define RECSM_H0  65536
#define RECSM_H1  (65536 + 8192)
#define RECSM_SG  (65536 + 16384)
#define REC_SMEM_BYTES (65536 + 16384 + 2048)

__global__ void __cluster_dims__(8, 1, 1) __launch_bounds__(256, 1)
lstm_rec_kernel(const float* __restrict__ xg,
                const float* __restrict__ Whh,
                const float* __restrict__ hInit,
                const float* __restrict__ cInit,
                __half* __restrict__ ysh,
                float* __restrict__ hFin,
                float* __restrict__ cFin,
                int nSteps) {
    extern __shared__ char smb[];
    const uint32_t sb = smem_u32(smb);
    float* sg = (float*)(smb + RECSM_SG);

    const int tid = threadIdx.x;
    const int lane = tid & 31;
    const int wid = tid >> 5;
    uint32_t rank;
    asm("mov.u32 %0, %%cluster_ctarank;" : "=r"(rank));
    const int bt = blockIdx.x >> 3;
    const int n0 = (int)rank * 32;

    for (int i = tid; i < 4096; i += 256)
        ((uint32_t*)(smb + RECSM_H0))[i] = 0u;

#pragma unroll 4
    for (int it = 0; it < 32; it++) {
        int idx = it * 256 + tid;
        int r = idx >> 6, c4 = idx & 63;
        int grow = (r >> 5) * 256 + n0 + (r & 31);
        float4 v = *(const float4*)(Whh + (size_t)grow * 256 + c4 * 4);
        int k = c4 * 4;
        int chunk = (k >> 3) ^ (r & 7);
        __half2* d = (__half2*)(smb + RECSM_W + r * 512 + chunk * 16 + (k & 7) * 2);
        d[0] = __floats2half2_rn(v.x, v.y);
        d[1] = __floats2half2_rn(v.z, v.w);
    }
    __syncthreads();

    if (hInit) {
        int b = tid >> 6, k = (tid & 63) * 4;
        float4 v = *(const float4*)(hInit + (size_t)(bt * 4 + b) * 256 + k);
        int chunk = (k >> 3) ^ b;
        __half2* d = (__half2*)(smb + RECSM_H0 + b * 512 + chunk * 16 + (k & 7) * 2);
        d[0] = __floats2half2_rn(v.x, v.y);
        d[1] = __floats2half2_rn(v.z, v.w);
    }

    const int fb = tid >> 5;
    const int fn = tid & 31;
    const int bG = bt * 4 + fb;
    float cS = 0.f;
    if (tid < 128 && cInit) cS = cInit[bG * 256 + n0 + fn];

    uint32_t remA[8], remB[8];
    if (tid < 128) {
        int kg = n0 + fn;
        uint32_t off = (uint32_t)(fb * 512 + (((kg >> 3) ^ fb) << 4) + (kg & 7) * 2);
        uint32_t la = sb + RECSM_H0 + off;
        uint32_t lb = sb + RECSM_H1 + off;
#pragma unroll
        for (int r = 0; r < 8; r++) {
            asm("mapa.shared::cluster.u32 %0, %1, %2;" : "=r"(remA[r]) : "r"(la), "r"(r));
            asm("mapa.shared::cluster.u32 %0, %1, %2;" : "=r"(remB[r]) : "r"(lb), "r"(r));
        }
    }
    __syncthreads();
    asm volatile("barrier.cluster.arrive.aligned;" ::: "memory");
    asm volatile("barrier.cluster.wait.aligned;" ::: "memory");

    const int nrow = wid * 16 + ((lane >> 4) & 1) * 8 + (lane & 7);
    const uint32_t bAddrBase = sb + RECSM_W + nrow * 512;
    const int brow7 = nrow & 7;
    const int arow = lane & 15;
    const int asel = lane >> 4;

    int p = 0;
    for (int step = 0; step < nSteps; step++) {
        float gi = 0.f, gf = 0.f, gg = 0.f, go = 0.f;
        size_t row = 0;
        if (tid < 128) {
            row = (size_t)step * 64 + bG;
            const float* xr = xg + row * 1024 + n0 + fn;
            gi = xr[0]; gf = xr[256]; gg = xr[512]; go = xr[768];
        }

        const uint32_t hbase = sb + (p ? RECSM_H1 : RECSM_H0) + arow * 512;
        const int arow7 = arow & 7;

        float acc0[4] = {0.f, 0.f, 0.f, 0.f};
        float acc1[4] = {0.f, 0.f, 0.f, 0.f};
#pragma unroll
        for (int kk = 0; kk < 16; kk++) {
            uint32_t a[4];
            ldsm4(a[0], a[1], a[2], a[3],
                  hbase + (uint32_t)(((kk * 2 + asel) ^ arow7) << 4));
            uint32_t b0, b1, b2, b3;
            ldsm4(b0, b1, b2, b3,
                  bAddrBase + (uint32_t)(((kk * 2 + ((lane >> 3) & 1)) ^ brow7) << 4));
            mma16816(acc0, a, b0, b1);
            mma16816(acc1, a, b2, b3);
        }

        if (lane < 16) {
            int g = wid >> 1, b = lane >> 2;
            int jb = (wid & 1) * 16 + (lane & 3) * 2;
            *(float2*)&sg[(g * 4 + b) * 32 + jb] = make_float2(acc0[0], acc0[1]);
            *(float2*)&sg[(g * 4 + b) * 32 + jb + 8] = make_float2(acc1[0], acc1[1]);
        }
        __syncthreads();

        float h = 0.f;
        if (tid < 128) {
            gi += sg[(0 * 4 + fb) * 32 + fn];
            gf += sg[(1 * 4 + fb) * 32 + fn];
            gg += sg[(2 * 4 + fb) * 32 + fn];
            go += sg[(3 * 4 + fb) * 32 + fn];
            float iv = 1.f / (1.f + expf(-gi));
            float fv = 1.f / (1.f + expf(-gf));
            float gv = tanhf(gg);
            float ov = 1.f / (1.f + expf(-go));
            cS = fv * cS + iv * gv;
            h = ov * tanhf(cS);

            unsigned short hu = __half_as_ushort(__float2half(h));
#pragma unroll
            for (int r = 0; r < 8; r++) {
                uint32_t ra = p ? remA[r] : remB[r];
                asm volatile("st.shared::cluster.u16 [%0], %1;" :: "r"(ra), "h"(hu) : "memory");
            }
        }

        asm volatile("barrier.cluster.arrive.aligned;" ::: "memory");
        if (tid < 128) {
            if (ysh) ysh[row * 256 + n0 + fn] = __float2half(h);
            if (step == nSteps - 1) {
                if (hFin) hFin[bG * 256 + n0 + fn] = h;
                if (cFin) cFin[bG * 256 + n0 + fn] = cS;
            }
        }
        asm volatile("barrier.cluster.wait.aligned;" ::: "memory");
        p ^= 1;
    }
}

// ---------------- host launch ----------------
extern "C" void kernel_launch(void* const* d_in, const int* in_sizes, int n_in,
                              void* d_out, int out_size) {
    const int*   src     = (const int*)d_in[0];
    const int*   trg     = (const int*)d_in[1];
    const float* enc_emb = (const float*)d_in[2];
    const float* dec_emb = (const float*)d_in[3];
    const float* eWih0 = (const float*)d_in[4],  *eWhh0 = (const float*)d_in[5];
    const float* ebih0 = (const float*)d_in[6],  *ebhh0 = (const float*)d_in[7];
    const float* eWih1 = (const float*)d_in[8],  *eWhh1 = (const float*)d_in[9];
    const float* ebih1 = (const float*)d_in[10], *ebhh1 = (const float*)d_in[11];
    const float* dWih0 = (const float*)d_in[12], *dWhh0 = (const float*)d_in[13];
    const float* dbih0 = (const float*)d_in[14], *dbhh0 = (const float*)d_in[15];
    const float* dWih1 = (const float*)d_in[16], *dWhh1 = (const float*)d_in[17];
    const float* dbih1 = (const float*)d_in[18], *dbhh1 = (const float*)d_in[19];
    const float* fcW   = (const float*)d_in[20], *fcb   = (const float*)d_in[21];
    float* out = (float*)d_out;

    float *pxg, *pxg2, *phF, *pcF, *phT;
    __half *pxh, *pxh2, *pyh, *pw0, *pw1, *pw2, *pw3, *pfw;
    cudaGetSymbolAddress((void**)&pxg,   g_xg);
    cudaGetSymbolAddress((void**)&pxg2,  g_xg2);
    cudaGetSymbolAddress((void**)&phF,   g_hF);
    cudaGetSymbolAddress((void**)&pcF,   g_cF);
    cudaGetSymbolAddress((void**)&phT,   g_hT);
    cudaGetSymbolAddress((void**)&pxh,   g_xh);
    cudaGetSymbolAddress((void**)&pxh2,  g_xh2);
    cudaGetSymbolAddress((void**)&pyh,   g_yh);
    cudaGetSymbolAddress((void**)&pw0,   g_w0);
    cudaGetSymbolAddress((void**)&pw1,   g_w1);
    cudaGetSymbolAddress((void**)&pw2,   g_w2);
    cudaGetSymbolAddress((void**)&pw3,   g_w3);
    cudaGetSymbolAddress((void**)&pfw,   g_fw);

    float* hT0 = phT;
    float* cT0 = phT + NB * NH;
    float* hT1 = phT + 2 * NB * NH;
    float* cT1 = phT + 3 * NB * NH;

    cudaFuncSetAttribute(lstm_rec_kernel,
                         cudaFuncAttributeMaxDynamicSharedMemorySize, REC_SMEM_BYTES);
    cudaFuncSetAttribute(gemm16_kernel,
                         cudaFuncAttributeMaxDynamicSharedMemorySize, GSMEM);
    cudaFuncSetAttribute(fc32_kernel,
                         cudaFuncAttributeMaxDynamicSharedMemorySize, GSMEM);

    // fallback (should already exist via static ctor)
    if (!g_sh.s) {
        cudaStreamCreateWithFlags(&g_sh.s, cudaStreamNonBlocking);
        cudaEventCreateWithFlags(&g_sh.e0, cudaEventDisableTiming);
        cudaEventCreateWithFlags(&g_sh.e1, cudaEventDisableTiming);
        cudaEventCreateWithFlags(&g_sh.e2, cudaEventDisableTiming);
    }

    // ---- setup ----
    f2h_all_kernel<<<(8978432 / 4 + 255) / 256, 256>>>(eWih0, eWih1, dWih0, dWih1, fcW,
                                                       pw0, pw1, pw2, pw3, pfw);
    zero_first_kernel<<<(NB * NV + 255) / 256, 256>>>(out);
    embed_src_kernel<<<(NSX * NB * NE + 255) / 256, 256>>>(src, enc_emb, pxh);
    embed_trg_kernel<<<(127 * NB * NE + 255) / 256, 256>>>(trg, dec_emb, pxh2);

    // fork: dec L0 gates on stream B (overlaps encoder); writes pxg2 (no conflict)
    cudaEventRecord(g_sh.e0, 0);
    cudaStreamWaitEvent(g_sh.s, g_sh.e0, 0);
    gemm16_kernel<<<dim3(16, 64), 256, GSMEM, g_sh.s>>>(pxh2, pw2, dbih0, dbhh0, pxg2,
                                                        G4, NE);
    cudaEventRecord(g_sh.e1, g_sh.s);

    // ---- Encoder (main) ----
    gemm16_kernel<<<dim3(16, 64), 256, GSMEM>>>(pxh, pw0, ebih0, ebhh0, pxg, G4, NE);
    lstm_rec_kernel<<<128, 256, REC_SMEM_BYTES>>>(pxg, eWhh0, nullptr, nullptr,
                                                  pyh, phF, pcF, 128);
    gemm16_kernel<<<dim3(16, 64), 256, GSMEM>>>(pyh, pw1, ebih1, ebhh1, pxg, G4, NH);
    lstm_rec_kernel<<<128, 256, REC_SMEM_BYTES>>>(pxg, eWhh1, nullptr, nullptr,
                                                  nullptr, phF + NB * NH, pcF + NB * NH,
                                                  128);

    // ---- Decoder chunk 1 (steps 0..63) ----
    cudaStreamWaitEvent(0, g_sh.e1, 0);     // dec L0 gates ready
    lstm_rec_kernel<<<128, 256, REC_SMEM_BYTES>>>(pxg2, dWhh0, phF, pcF,
                                                  pyh, hT0, cT0, CH1);
    gemm16_kernel<<<dim3(16, 32), 256, GSMEM>>>(pyh, pw3, dbih1, dbhh1, pxg, G4, NH);
    lstm_rec_kernel<<<128, 256, REC_SMEM_BYTES>>>(pxg, dWhh1, phF + NB * NH, pcF + NB * NH,
                                                  pyh, hT1, cT1, CH1);

    // fork: FC half A (rows < 4096) on stream B, overlapping chunk 2 on main
    cudaEventRecord(g_sh.e2, 0);
    cudaStreamWaitEvent(g_sh.s, g_sh.e2, 0);
    fc32_kernel<<<dim3(500, 32), 256, GSMEM, g_sh.s>>>(pyh, pfw, fcb, out, 0);
    cudaEventRecord(g_sh.e1, g_sh.s);

    // ---- Decoder chunk 2 (steps 64..126) on main ----
    lstm_rec_kernel<<<128, 256, REC_SMEM_BYTES>>>(pxg2 + (size_t)OFFR * 1024, dWhh0,
                                                  hT0, cT0,
                                                  pyh + (size_t)OFFR * 256,
                                                  nullptr, nullptr, CH2);
    gemm16_kernel<<<dim3(16, 32), 256, GSMEM>>>(pyh + (size_t)OFFR * 256, pw3,
                                                dbih1, dbhh1,
                                                pxg + (size_t)OFFR * 1024, G4, NH);
    lstm_rec_kernel<<<128, 256, REC_SMEM_BYTES>>>(pxg + (size_t)OFFR * 1024, dWhh1,
                                                  hT1, cT1,
                                                  pyh + (size_t)OFFR * 256,
                                                  nullptr, nullptr, CH2);

    // ---- FC half B (rows >= 4096) on main, concurrent with tail of FC A ----
    fc32_kernel<<<dim3(500, 32), 256, GSMEM>>>(pyh, pfw, fcb, out, 32);

    // join stream B back into main before returning
    cudaStreamWaitEvent(0, g_sh.e1, 0);
}

// round 15
// speedup vs baseline: 1.1687x; 1.1080x over previous
#include <cuda_runtime.h>
#include <cuda_fp16.h>
#include <cstdint>
#include <math.h>

// Problem constants
#define NB 64
#define NSX 128
#define NT 128
#define NE 128
#define NH 256
#define NV 32000
#define G4 1024
#define CH1 64                  // decoder chunk-1 steps
#define CH2 63                  // decoder chunk-2 steps
#define OFFR 4096               // rows in chunk 1 (CH1*64)

// ---------------- device scratch ----------------
__device__ float  g_xg [8192 * G4];         // xg buffer A (32 MB)
__device__ float  g_xg2[8192 * G4];         // xg buffer B (32 MB)
__device__ __half g_xh [8192 * NE];         // fp16 embedded enc inputs
__device__ __half g_xh2[8192 * NE];         // fp16 embedded dec inputs
__device__ __half g_yh [8192 * NH];         // fp16 layer outputs (enc L0, dec L1)
__device__ __half g_yh2[8192 * NH];         // fp16 dec L0 outputs
__device__ float  g_hF[2 * NB * NH];
__device__ float  g_cF[2 * NB * NH];
__device__ float  g_hT[4 * NB * NH];        // chunk-carry states: hT0,cT0,hT1,cT1
__device__ __half g_w0[G4 * NE];
__device__ __half g_w1[G4 * NH];
__device__ __half g_w2[G4 * NE];
__device__ __half g_w3[G4 * NH];
__device__ __half g_fw[NV * NH];

// ---------------- stream/event resources (created pre-main) ----------------
struct StreamHolder {
    cudaStream_t b = nullptr, c = nullptr;
    cudaEvent_t ev[8] = {};
    StreamHolder() {
        cudaStreamCreateWithFlags(&b, cudaStreamNonBlocking);
        cudaStreamCreateWithFlags(&c, cudaStreamNonBlocking);
        for (int i = 0; i < 8; i++)
            cudaEventCreateWithFlags(&ev[i], cudaEventDisableTiming);
    }
};
static StreamHolder g_sh;

// ---------------- small helpers ----------------
__device__ __forceinline__ uint32_t smem_u32(const void* p) {
    uint32_t a;
    asm("{ .reg .u64 t; cvta.to.shared.u64 t, %1; cvt.u32.u64 %0, t; }"
        : "=r"(a) : "l"(p));
    return a;
}
__device__ __forceinline__ void cp16(uint32_t dst, const void* src) {
    asm volatile("cp.async.cg.shared.global [%0], [%1], 16;" :: "r"(dst), "l"(src));
}
__device__ __forceinline__ void ldsm4(uint32_t& r0, uint32_t& r1, uint32_t& r2,
                                      uint32_t& r3, uint32_t addr) {
    asm volatile("ldmatrix.sync.aligned.m8n8.x4.shared.b16 {%0,%1,%2,%3}, [%4];"
                 : "=r"(r0), "=r"(r1), "=r"(r2), "=r"(r3) : "r"(addr));
}
__device__ __forceinline__ void mma16816(float* c, const uint32_t* a,
                                         uint32_t b0, uint32_t b1) {
    asm volatile(
        "mma.sync.aligned.m16n8k16.row.col.f32.f16.f16.f32 "
        "{%0,%1,%2,%3}, {%4,%5,%6,%7}, {%8,%9}, {%0,%1,%2,%3};"
        : "+f"(c[0]), "+f"(c[1]), "+f"(c[2]), "+f"(c[3])
        : "r"(a[0]), "r"(a[1]), "r"(a[2]), "r"(a[3]), "r"(b0), "r"(b1));
}

// ---------------- conversion kernels ----------------
// small: the 4 gate-weight matrices (786432 floats)
__global__ void f2h_small_kernel(const float* __restrict__ e0, const float* __restrict__ e1,
                                 const float* __restrict__ q0, const float* __restrict__ q1,
                                 __half* __restrict__ w0, __half* __restrict__ w1,
                                 __half* __restrict__ w2, __half* __restrict__ w3) {
    int i = (blockIdx.x * blockDim.x + threadIdx.x) * 4;
    const float* s; __half* d; int off;
    if (i < 131072)      { s = e0; d = w0; off = i; }
    else if (i < 393216) { s = e1; d = w1; off = i - 131072; }
    else if (i < 524288) { s = q0; d = w2; off = i - 393216; }
    else if (i < 786432) { s = q1; d = w3; off = i - 524288; }
    else return;
    float4 v = *(const float4*)(s + off);
    __half2* o = (__half2*)(d + off);
    o[0] = __floats2half2_rn(v.x, v.y);
    o[1] = __floats2half2_rn(v.z, v.w);
}

__global__ void f2h_fcw_kernel(const float* __restrict__ s, __half* __restrict__ d) {
    int i = (blockIdx.x * blockDim.x + threadIdx.x) * 4;
    if (i >= NV * NH) return;
    float4 v = *(const float4*)(s + i);
    __half2* o = (__half2*)(d + i);
    o[0] = __floats2half2_rn(v.x, v.y);
    o[1] = __floats2half2_rn(v.z, v.w);
}

// ---------------- embedding kernels ----------------
__global__ void embed_src_kernel(const int* __restrict__ src,
                                 const float* __restrict__ emb,
                                 __half* __restrict__ out) {
    int idx = blockIdx.x * blockDim.x + threadIdx.x;
    if (idx >= NSX * NB * NE) return;
    int e = idx % NE;
    int r = idx / NE;
    int b = r % NB;
    int s = r / NB;
    out[(size_t)r * NE + e] = __float2half(emb[(size_t)src[b * NSX + s] * NE + e]);
}

__global__ void embed_trg_kernel(const int* __restrict__ trg,
                                 const float* __restrict__ emb,
                                 __half* __restrict__ out) {
    int idx = blockIdx.x * blockDim.x + threadIdx.x;
    if (idx >= 127 * NB * NE) return;
    int e = idx % NE;
    int r = idx / NE;
    int b = r % NB;
    int t = r / NB;
    int tok = (t == 0) ? 1 : trg[b * NT + t];
    out[(size_t)r * NE + e] = __float2half(emb[(size_t)tok * NE + e]);
}

__global__ void zero_first_kernel(float* __restrict__ out) {
    int idx = blockIdx.x * blockDim.x + threadIdx.x;
    if (idx >= NB * NV) return;
    int v = idx % NV;
    int b = idx / NV;
    out[(size_t)b * NT * NV + v] = 0.f;
}

// ---------------- fp16 tensor-core GEMM for gates (fp32 acc) ----------------
#define GSTAGE 24576                  // A 16KB + B 8KB
#define GSMEM  (3 * GSTAGE)

__global__ void __launch_bounds__(256, 3)
gemm16_kernel(const __half* __restrict__ A, const __half* __restrict__ W,
              const float* __restrict__ b0, const float* __restrict__ b1,
              float* __restrict__ C, int N, int K) {
    extern __shared__ char smbuf[];
    const uint32_t sb = smem_u32(smbuf);
    const int tid = threadIdx.x;
    const int lane = tid & 31;
    const int wid = tid >> 5;
    const int warp_m = wid & 3;
    const int warp_n = wid >> 2;
    const int m0 = blockIdx.y * 128;
    const int n0 = blockIdx.x * 64;
    const int KT = K >> 6;

    float acc[2][4][4];
#pragma unroll
    for (int i = 0; i < 2; i++)
#pragma unroll
        for (int j = 0; j < 4; j++)
#pragma unroll
            for (int q = 0; q < 4; q++) acc[i][j][q] = 0.f;

    auto loadStage = [&](int kt, int s) {
        const uint32_t st = sb + (uint32_t)s * GSTAGE;
        const __half* Ag = A + (size_t)m0 * K + kt * 64;
        const __half* Wg = W + (size_t)n0 * K + kt * 64;
#pragma unroll
        for (int i = 0; i < 4; i++) {
            int idx = i * 256 + tid;
            int row = idx >> 3, c = idx & 7;
            uint32_t off = (uint32_t)(row * 128 + ((c ^ (row & 7)) << 4));
            cp16(st + off, Ag + (size_t)row * K + c * 8);
        }
#pragma unroll
        for (int i = 0; i < 2; i++) {
            int idx = i * 256 + tid;
            int row = idx >> 3, c = idx & 7;
            uint32_t off = (uint32_t)(row * 128 + ((c ^ (row & 7)) << 4));
            cp16(st + 16384 + off, Wg + (size_t)row * K + c * 8);
        }
        asm volatile("cp.async.commit_group;" ::: "memory");
    };

    loadStage(0, 0);
    loadStage(1, 1);
    asm volatile("cp.async.wait_group 1;" ::: "memory");
    __syncthreads();

    for (int kt = 0; kt < KT; kt++) {
        const int s = kt % 3;
        if (kt + 2 < KT) loadStage(kt + 2, (kt + 2) % 3);
        const uint32_t stA = sb + (uint32_t)s * GSTAGE;
        const uint32_t stB = stA + 16384;
#pragma unroll
        for (int k16 = 0; k16 < 4; k16++) {
            uint32_t a[2][4];
#pragma unroll
            for (int mt = 0; mt < 2; mt++) {
                int row = warp_m * 32 + mt * 16 + (lane & 15);
                int ch = k16 * 2 + (lane >> 4);
                ldsm4(a[mt][0], a[mt][1], a[mt][2], a[mt][3],
                      stA + row * 128 + ((ch ^ (row & 7)) << 4));
            }
#pragma unroll
            for (int p = 0; p < 2; p++) {
                int nrow = warp_n * 32 + p * 16 + ((lane >> 4) & 1) * 8 + (lane & 7);
                int ch = k16 * 2 + ((lane >> 3) & 1);
                uint32_t br0, br1, br2, br3;
                ldsm4(br0, br1, br2, br3,
                      stB + nrow * 128 + ((ch ^ (nrow & 7)) << 4));
#pragma unroll
                for (int mt = 0; mt < 2; mt++) {
                    mma16816(acc[mt][2 * p],     a[mt], br0, br1);
                    mma16816(acc[mt][2 * p + 1], a[mt], br2, br3);
                }
            }
        }
        asm volatile("cp.async.wait_group 1;" ::: "memory");
        __syncthreads();
    }

    const int lrow = lane >> 2;
    const int lcol = (lane & 3) * 2;
#pragma unroll
    for (int nt = 0; nt < 4; nt++) {
        const int n = n0 + warp_n * 32 + nt * 8 + lcol;
        float bv0 = b0[n] + b1[n];
        float bv1 = b0[n + 1] + b1[n + 1];
#pragma unroll
        for (int mt = 0; mt < 2; mt++) {
            const int mbase = m0 + warp_m * 32 + mt * 16 + lrow;
#pragma unroll
            for (int half = 0; half < 2; half++) {
                const int m = mbase + half * 8;
                float2 v;
                v.x = acc[mt][nt][half * 2 + 0] + bv0;
                v.y = acc[mt][nt][half * 2 + 1] + bv1;
                *(float2*)(C + (size_t)m * N + n) = v;
            }
        }
    }
}

// ---------------- FC GEMM (fp32 acc, K=256, M-tile offset) ----------------
__global__ void __launch_bounds__(256, 3)
fc32_kernel(const __half* __restrict__ A, const __half* __restrict__ W,
            const float* __restrict__ bias, float* __restrict__ C, int mTile0) {
    extern __shared__ char smbuf[];
    const uint32_t sb = smem_u32(smbuf);
    const int tid = threadIdx.x;
    const int lane = tid & 31;
    const int wid = tid >> 5;
    const int warp_m = wid & 3;
    const int warp_n = wid >> 2;
    const int m0 = (mTile0 + blockIdx.y) * 128;
    const int n0 = blockIdx.x * 64;
    const int K = 256;

    float acc[2][4][4];
#pragma unroll
    for (int i = 0; i < 2; i++)
#pragma unroll
        for (int j = 0; j < 4; j++)
#pragma unroll
            for (int q = 0; q < 4; q++) acc[i][j][q] = 0.f;

    auto loadStage = [&](int kt, int s) {
        const uint32_t st = sb + (uint32_t)s * GSTAGE;
        const __half* Ag = A + (size_t)m0 * K + kt * 64;
        const __half* Wg = W + (size_t)n0 * K + kt * 64;
#pragma unroll
        for (int i = 0; i < 4; i++) {
            int idx = i * 256 + tid;
            int row = idx >> 3, c = idx & 7;
            uint32_t off = (uint32_t)(row * 128 + ((c ^ (row & 7)) << 4));
            cp16(st + off, Ag + (size_t)row * K + c * 8);
        }
#pragma unroll
        for (int i = 0; i < 2; i++) {
            int idx = i * 256 + tid;
            int row = idx >> 3, c = idx & 7;
            uint32_t off = (uint32_t)(row * 128 + ((c ^ (row & 7)) << 4));
            cp16(st + 16384 + off, Wg + (size_t)row * K + c * 8);
        }
        asm volatile("cp.async.commit_group;" ::: "memory");
    };

    loadStage(0, 0);
    loadStage(1, 1);
    asm volatile("cp.async.wait_group 1;" ::: "memory");
    __syncthreads();

#pragma unroll
    for (int kt = 0; kt < 4; kt++) {
        const int s = kt % 3;
        if (kt + 2 < 4) loadStage(kt + 2, (kt + 2) % 3);
        const uint32_t stA = sb + (uint32_t)s * GSTAGE;
        const uint32_t stB = stA + 16384;
#pragma unroll
        for (int k16 = 0; k16 < 4; k16++) {
            uint32_t a[2][4];
#pragma unroll
            for (int mt = 0; mt < 2; mt++) {
                int row = warp_m * 32 + mt * 16 + (lane & 15);
                int ch = k16 * 2 + (lane >> 4);
                ldsm4(a[mt][0], a[mt][1], a[mt][2], a[mt][3],
                      stA + row * 128 + ((ch ^ (row & 7)) << 4));
            }
#pragma unroll
            for (int p = 0; p < 2; p++) {
                int nrow = warp_n * 32 + p * 16 + ((lane >> 4) & 1) * 8 + (lane & 7);
                int ch = k16 * 2 + ((lane >> 3) & 1);
                uint32_t br0, br1, br2, br3;
                ldsm4(br0, br1, br2, br3,
                      stB + nrow * 128 + ((ch ^ (nrow & 7)) << 4));
#pragma unroll
                for (int mt = 0; mt < 2; mt++) {
                    mma16816(acc[mt][2 * p],     a[mt], br0, br1);
                    mma16816(acc[mt][2 * p + 1], a[mt], br2, br3);
                }
            }
        }
        asm volatile("cp.async.wait_group 1;" ::: "memory");
        __syncthreads();
    }

    const int lrow = lane >> 2;
    const int lcol = (lane & 3) * 2;
#pragma unroll
    for (int nt = 0; nt < 4; nt++) {
        const int n = n0 + warp_n * 32 + nt * 8 + lcol;
        float bv0 = bias[n];
        float bv1 = bias[n + 1];
#pragma unroll
        for (int mt = 0; mt < 2; mt++) {
            const int mbase = m0 + warp_m * 32 + mt * 16 + lrow;
#pragma unroll
            for (int half = 0; half < 2; half++) {
                const int m = mbase + half * 8;
                if (m < 8128) {
                    int t = m >> 6, b = m & 63;
                    float2 v;
                    v.x = acc[mt][nt][half * 2 + 0] + bv0;
                    v.y = acc[mt][nt][half * 2 + 1] + bv1;
                    *(float2*)(C + ((size_t)(b * 128 + t + 1)) * NV + n) = v;
                }
            }
        }
    }
}

// ---------------- clustered HMMA LSTM recurrence (occupancy 2 for co-run) ----------------
#define RECSM_W   0
#define RECSM_H0  65536
#define RECSM_H1  (65536 + 8192)
#define RECSM_SG  (65536 + 16384)
#define REC_SMEM_BYTES (65536 + 16384 + 2048)

__global__ void __cluster_dims__(8, 1, 1) __launch_bounds__(256, 2)
lstm_rec_kernel(const float* __restrict__ xg,
                const float* __restrict__ Whh,
                const float* __restrict__ hInit,
                const float* __restrict__ cInit,
                __half* __restrict__ ysh,
                float* __restrict__ hFin,
                float* __restrict__ cFin,
                int nSteps) {
    extern __shared__ char smb[];
    const uint32_t sb = smem_u32(smb);
    float* sg = (float*)(smb + RECSM_SG);

    const int tid = threadIdx.x;
    const int lane = tid & 31;
    const int wid = tid >> 5;
    uint32_t rank;
    asm("mov.u32 %0, %%cluster_ctarank;" : "=r"(rank));
    const int bt = blockIdx.x >> 3;
    const int n0 = (int)rank * 32;

    for (int i = tid; i < 4096; i += 256)
        ((uint32_t*)(smb + RECSM_H0))[i] = 0u;

#pragma unroll 4
    for (int it = 0; it < 32; it++) {
        int idx = it * 256 + tid;
        int r = idx >> 6, c4 = idx & 63;
        int grow = (r >> 5) * 256 + n0 + (r & 31);
        float4 v = *(const float4*)(Whh + (size_t)grow * 256 + c4 * 4);
        int k = c4 * 4;
        int chunk = (k >> 3) ^ (r & 7);
        __half2* d = (__half2*)(smb + RECSM_W + r * 512 + chunk * 16 + (k & 7) * 2);
        d[0] = __floats2half2_rn(v.x, v.y);
        d[1] = __floats2half2_rn(v.z, v.w);
    }
    __syncthreads();

    if (hInit) {
        int b = tid >> 6, k = (tid & 63) * 4;
        float4 v = *(const float4*)(hInit + (size_t)(bt * 4 + b) * 256 + k);
        int chunk = (k >> 3) ^ b;
        __half2* d = (__half2*)(smb + RECSM_H0 + b * 512 + chunk * 16 + (k & 7) * 2);
        d[0] = __floats2half2_rn(v.x, v.y);
        d[1] = __floats2half2_rn(v.z, v.w);
    }

    const int fb = tid >> 5;
    const int fn = tid & 31;
    const int bG = bt * 4 + fb;
    float cS = 0.f;
    if (tid < 128 && cInit) cS = cInit[bG * 256 + n0 + fn];

    uint32_t remA[8], remB[8];
    if (tid < 128) {
        int kg = n0 + fn;
        uint32_t off = (uint32_t)(fb * 512 + (((kg >> 3) ^ fb) << 4) + (kg & 7) * 2);
        uint32_t la = sb + RECSM_H0 + off;
        uint32_t lb = sb + RECSM_H1 + off;
#pragma unroll
        for (int r = 0; r < 8; r++) {
            asm("mapa.shared::cluster.u32 %0, %1, %2;" : "=r"(remA[r]) : "r"(la), "r"(r));
            asm("mapa.shared::cluster.u32 %0, %1, %2;" : "=r"(remB[r]) : "r"(lb), "r"(r));
        }
    }
    __syncthreads();
    asm volatile("barrier.cluster.arrive.aligned;" ::: "memory");
    asm volatile("barrier.cluster.wait.aligned;" ::: "memory");

    const int nrow = wid * 16 + ((lane >> 4) & 1) * 8 + (lane & 7);
    const uint32_t bAddrBase = sb + RECSM_W + nrow * 512;
    const int brow7 = nrow & 7;
    const int arow = lane & 15;
    const int asel = lane >> 4;

    int p = 0;
    for (int step = 0; step < nSteps; step++) {
        float gi = 0.f, gf = 0.f, gg = 0.f, go = 0.f;
        size_t row = 0;
        if (tid < 128) {
            row = (size_t)step * 64 + bG;
            const float* xr = xg + row * 1024 + n0 + fn;
            gi = xr[0]; gf = xr[256]; gg = xr[512]; go = xr[768];
        }

        const uint32_t hbase = sb + (p ? RECSM_H1 : RECSM_H0) + arow * 512;
        const int arow7 = arow & 7;

        float acc0[4] = {0.f, 0.f, 0.f, 0.f};
        float acc1[4] = {0.f, 0.f, 0.f, 0.f};
#pragma unroll
        for (int kk = 0; kk < 16; kk++) {
            uint32_t a[4];
            ldsm4(a[0], a[1], a[2], a[3],
                  hbase + (uint32_t)(((kk * 2 + asel) ^ arow7) << 4));
            uint32_t b0, b1, b2, b3;
            ldsm4(b0, b1, b2, b3,
                  bAddrBase + (uint32_t)(((kk * 2 + ((lane >> 3) & 1)) ^ brow7) << 4));
            mma16816(acc0, a, b0, b1);
            mma16816(acc1, a, b2, b3);
        }

        if (lane < 16) {
            int g = wid >> 1, b = lane >> 2;
            int jb = (wid & 1) * 16 + (lane & 3) * 2;
            *(float2*)&sg[(g * 4 + b) * 32 + jb] = make_float2(acc0[0], acc0[1]);
            *(float2*)&sg[(g * 4 + b) * 32 + jb + 8] = make_float2(acc1[0], acc1[1]);
        }
        __syncthreads();

        float h = 0.f;
        if (tid < 128) {
            gi += sg[(0 * 4 + fb) * 32 + fn];
            gf += sg[(1 * 4 + fb) * 32 + fn];
            gg += sg[(2 * 4 + fb) * 32 + fn];
            go += sg[(3 * 4 + fb) * 32 + fn];
            float iv = 1.f / (1.f + expf(-gi));
            float fv = 1.f / (1.f + expf(-gf));
            float gv = tanhf(gg);
            float ov = 1.f / (1.f + expf(-go));
            cS = fv * cS + iv * gv;
            h = ov * tanhf(cS);

            unsigned short hu = __half_as_ushort(__float2half(h));
#pragma unroll
            for (int r = 0; r < 8; r++) {
                uint32_t ra = p ? remA[r] : remB[r];
                asm volatile("st.shared::cluster.u16 [%0], %1;" :: "r"(ra), "h"(hu) : "memory");
            }
        }

        asm volatile("barrier.cluster.arrive.aligned;" ::: "memory");
        if (tid < 128) {
            if (ysh) ysh[row * 256 + n0 + fn] = __float2half(h);
            if (step == nSteps - 1) {
                if (hFin) hFin[bG * 256 + n0 + fn] = h;
                if (cFin) cFin[bG * 256 + n0 + fn] = cS;
            }
        }
        asm volatile("barrier.cluster.wait.aligned;" ::: "memory");
        p ^= 1;
    }
}

// ---------------- host launch ----------------
extern "C" void kernel_launch(void* const* d_in, const int* in_sizes, int n_in,
                              void* d_out, int out_size) {
    const int*   src     = (const int*)d_in[0];
    const int*   trg     = (const int*)d_in[1];
    const float* enc_emb = (const float*)d_in[2];
    const float* dec_emb = (const float*)d_in[3];
    const float* eWih0 = (const float*)d_in[4],  *eWhh0 = (const float*)d_in[5];
    const float* ebih0 = (const float*)d_in[6],  *ebhh0 = (const float*)d_in[7];
    const float* eWih1 = (const float*)d_in[8],  *eWhh1 = (const float*)d_in[9];
    const float* ebih1 = (const float*)d_in[10], *ebhh1 = (const float*)d_in[11];
    const float* dWih0 = (const float*)d_in[12], *dWhh0 = (const float*)d_in[13];
    const float* dbih0 = (const float*)d_in[14], *dbhh0 = (const float*)d_in[15];
    const float* dWih1 = (const float*)d_in[16], *dWhh1 = (const float*)d_in[17];
    const float* dbih1 = (const float*)d_in[18], *dbhh1 = (const float*)d_in[19];
    const float* fcW   = (const float*)d_in[20], *fcb   = (const float*)d_in[21];
    float* out = (float*)d_out;

    float *pxg, *pxg2, *phF, *pcF, *phT;
    __half *pxh, *pxh2, *pyh, *pyh2, *pw0, *pw1, *pw2, *pw3, *pfw;
    cudaGetSymbolAddress((void**)&pxg,   g_xg);
    cudaGetSymbolAddress((void**)&pxg2,  g_xg2);
    cudaGetSymbolAddress((void**)&phF,   g_hF);
    cudaGetSymbolAddress((void**)&pcF,   g_cF);
    cudaGetSymbolAddress((void**)&phT,   g_hT);
    cudaGetSymbolAddress((void**)&pxh,   g_xh);
    cudaGetSymbolAddress((void**)&pxh2,  g_xh2);
    cudaGetSymbolAddress((void**)&pyh,   g_yh);
    cudaGetSymbolAddress((void**)&pyh2,  g_yh2);
    cudaGetSymbolAddress((void**)&pw0,   g_w0);
    cudaGetSymbolAddress((void**)&pw1,   g_w1);
    cudaGetSymbolAddress((void**)&pw2,   g_w2);
    cudaGetSymbolAddress((void**)&pw3,   g_w3);
    cudaGetSymbolAddress((void**)&pfw,   g_fw);

    float* hT0 = phT;
    float* cT0 = phT + NB * NH;
    float* hT1 = phT + 2 * NB * NH;
    float* cT1 = phT + 3 * NB * NH;

    cudaFuncSetAttribute(lstm_rec_kernel,
                         cudaFuncAttributeMaxDynamicSharedMemorySize, REC_SMEM_BYTES);
    cudaFuncSetAttribute(gemm16_kernel,
                         cudaFuncAttributeMaxDynamicSharedMemorySize, GSMEM);
    cudaFuncSetAttribute(fc32_kernel,
                         cudaFuncAttributeMaxDynamicSharedMemorySize, GSMEM);

    if (!g_sh.b) {
        cudaStreamCreateWithFlags(&g_sh.b, cudaStreamNonBlocking);
        cudaStreamCreateWithFlags(&g_sh.c, cudaStreamNonBlocking);
        for (int i = 0; i < 8; i++)
            cudaEventCreateWithFlags(&g_sh.ev[i], cudaEventDisableTiming);
    }
    cudaStream_t sB = g_sh.b, sC = g_sh.c;
    cudaEvent_t* ev = g_sh.ev;

    // ---- setup on main ----
    f2h_small_kernel<<<(786432 / 4 + 255) / 256, 256>>>(eWih0, eWih1, dWih0, dWih1,
                                                        pw0, pw1, pw2, pw3);
    embed_src_kernel<<<(NSX * NB * NE + 255) / 256, 256>>>(src, enc_emb, pxh);
    embed_trg_kernel<<<(127 * NB * NE + 255) / 256, 256>>>(trg, dec_emb, pxh2);
    cudaEventRecord(ev[0], 0);                     // setup done

    // ---- stream C: heavy fcW convert + out zeroing (overlaps encoder) ----
    cudaStreamWaitEvent(sC, ev[0], 0);
    f2h_fcw_kernel<<<(NV * NH / 4 + 255) / 256, 256, 0, sC>>>(fcW, pfw);
    zero_first_kernel<<<(NB * NV + 255) / 256, 256, 0, sC>>>(out);

    // ---- stream B: dec L0 gates (overlaps encoder L0) ----
    cudaStreamWaitEvent(sB, ev[0], 0);
    gemm16_kernel<<<dim3(16, 64), 256, GSMEM, sB>>>(pxh2, pw2, dbih0, dbhh0, pxg2,
                                                    G4, NE);

    // ---- main: encoder L0 ----
    gemm16_kernel<<<dim3(16, 64), 256, GSMEM>>>(pxh, pw0, ebih0, ebhh0, pxg, G4, NE);
    lstm_rec_kernel<<<128, 256, REC_SMEM_BYTES>>>(pxg, eWhh0, nullptr, nullptr,
                                                  pyh, phF, pcF, 128);
    cudaEventRecord(ev[1], 0);                     // enc L0 done (eh0/ec0 ready)

    // ---- stream B: dec L0 recurrence (concurrent with encoder L1) ----
    cudaStreamWaitEvent(sB, ev[1], 0);
    lstm_rec_kernel<<<128, 256, REC_SMEM_BYTES, sB>>>(pxg2, dWhh0, phF, pcF,
                                                      pyh2, hT0, cT0, CH1);
    cudaEventRecord(ev[2], sB);                    // dec L0 chunk 1 done
    lstm_rec_kernel<<<128, 256, REC_SMEM_BYTES, sB>>>(pxg2 + (size_t)OFFR * 1024, dWhh0,
                                                      hT0, cT0,
                                                      pyh2 + (size_t)OFFR * 256,
                                                      nullptr, nullptr, CH2);
    cudaEventRecord(ev[3], sB);                    // dec L0 chunk 2 done

    // ---- main: encoder L1 ----
    gemm16_kernel<<<dim3(16, 64), 256, GSMEM>>>(pyh, pw1, ebih1, ebhh1, pxg, G4, NH);
    lstm_rec_kernel<<<128, 256, REC_SMEM_BYTES>>>(pxg, eWhh1, nullptr, nullptr,
                                                  nullptr, phF + NB * NH, pcF + NB * NH,
                                                  128);

    // ---- main: dec L1 chunk 1 ----
    cudaStreamWaitEvent(0, ev[2], 0);
    gemm16_kernel<<<dim3(16, 32), 256, GSMEM>>>(pyh2, pw3, dbih1, dbhh1, pxg, G4, NH);
    lstm_rec_kernel<<<128, 256, REC_SMEM_BYTES>>>(pxg, dWhh1, phF + NB * NH, pcF + NB * NH,
                                                  pyh, hT1, cT1, CH1);
    cudaEventRecord(ev[4], 0);                     // dec L1 chunk 1 done

    // ---- main: dec L1 chunk 2 ----
    cudaStreamWaitEvent(0, ev[3], 0);
    gemm16_kernel<<<dim3(16, 32), 256, GSMEM>>>(pyh2 + (size_t)OFFR * 256, pw3,
                                                dbih1, dbhh1,
                                                pxg + (size_t)OFFR * 1024, G4, NH);
    lstm_rec_kernel<<<128, 256, REC_SMEM_BYTES>>>(pxg + (size_t)OFFR * 1024, dWhh1,
                                                  hT1, cT1,
                                                  pyh + (size_t)OFFR * 256,
                                                  nullptr, nullptr, CH2);
    cudaEventRecord(ev[5], 0);                     // dec L1 chunk 2 done

    // ---- stream C: FC halves (fcW convert + zero already ordered on C) ----
    cudaStreamWaitEvent(sC, ev[4], 0);
    fc32_kernel<<<dim3(500, 32), 256, GSMEM, sC>>>(pyh, pfw, fcb, out, 0);
    cudaStreamWaitEvent(sC, ev[5], 0);
    fc32_kernel<<<dim3(500, 32), 256, GSMEM, sC>>>(pyh, pfw, fcb, out, 32);
    cudaEventRecord(ev[6], sC);

    // join
    cudaStreamWaitEvent(0, ev[6], 0);
}